// round 16
// baseline (speedup 1.0000x reference)
#include <cuda_runtime.h>
#include <cuda_fp16.h>
#include <math.h>
#include <stdint.h>

#define NL   32768
#define HDIM 768
#define KFAC 256
#define NCH  3
#define MDIM 3072

// ---------------------------------------------------------------------------
// Scratch
// ---------------------------------------------------------------------------
static const long S_H    = (long)NL * HDIM;
static const long S_QKV  = (long)NL * 3 * HDIM;
static const long S_HID  = (long)NL * MDIM;
static const long W1T_SZ = (long)HDIM * MDIM;
static const long WQT_SZ = (long)NCH * HDIM * KFAC;

__device__ __half g_half[260046848];
__device__ float  g_f32[25165824];

#define B_H    0L
#define B_CTX  (S_H)
#define B_Y    (2*S_H)
#define B_QKV  (3*S_H)
#define B_HID  (3*S_H + S_QKV)
#define B_W1T  (B_HID + S_HID)
#define B_W2T  (B_W1T + W1T_SZ)
#define B_WQT  (B_W2T + W1T_SZ)
#define B_WOT  (B_WQT + WQT_SZ)

// ---------------------------------------------------------------------------
// PTX helpers
// ---------------------------------------------------------------------------
__device__ __forceinline__ uint32_t smem_u32(const void* p) {
    uint32_t a;
    asm("{ .reg .u64 t; cvta.to.shared.u64 t, %1; cvt.u32.u64 %0, t; }" : "=r"(a) : "l"(p));
    return a;
}
#define CP_ASYNC16(dst, src) \
    asm volatile("cp.async.cg.shared.global [%0], [%1], 16;" :: "r"(dst), "l"(src))
#define CP_COMMIT() asm volatile("cp.async.commit_group;" ::: "memory")
#define CP_WAIT2()  asm volatile("cp.async.wait_group 2;" ::: "memory")

#define LDSM4(r0, r1, r2, r3, a) \
    asm volatile("ldmatrix.sync.aligned.m8n8.x4.shared.b16 {%0,%1,%2,%3}, [%4];" \
        : "=r"(r0), "=r"(r1), "=r"(r2), "=r"(r3) : "r"(a))

#define MMA_F16(c, a, b0, b1) \
    asm volatile("mma.sync.aligned.m16n8k16.row.col.f32.f16.f16.f32 " \
        "{%0,%1,%2,%3}, {%4,%5,%6,%7}, {%8,%9}, {%0,%1,%2,%3};" \
        : "+f"((c)[0]), "+f"((c)[1]), "+f"((c)[2]), "+f"((c)[3]) \
        : "r"((a)[0]), "r"((a)[1]), "r"((a)[2]), "r"((a)[3]), "r"(b0), "r"(b1))

// ---------------------------------------------------------------------------
// LayerNorm -> fp16
// ---------------------------------------------------------------------------
__global__ void ln_kernel(const float* __restrict__ X,
                          const float* __restrict__ gamma,
                          const float* __restrict__ beta,
                          __half* __restrict__ O)
{
    __shared__ float s1[8], s2[8];
    int row = blockIdx.x, t = threadIdx.x;
    const float* xr = X + (size_t)row * HDIM;
    float v0 = xr[t], v1 = xr[t + 256], v2 = xr[t + 512];
    float s  = v0 + v1 + v2;
    float ss = v0 * v0 + v1 * v1 + v2 * v2;
    #pragma unroll
    for (int o = 16; o > 0; o >>= 1) {
        s  += __shfl_down_sync(0xffffffffu, s, o);
        ss += __shfl_down_sync(0xffffffffu, ss, o);
    }
    if ((t & 31) == 0) { s1[t >> 5] = s; s2[t >> 5] = ss; }
    __syncthreads();
    if (t < 32) {
        float a = (t < 8) ? s1[t] : 0.f;
        float b = (t < 8) ? s2[t] : 0.f;
        #pragma unroll
        for (int o = 4; o > 0; o >>= 1) {
            a += __shfl_down_sync(0xffffffffu, a, o);
            b += __shfl_down_sync(0xffffffffu, b, o);
        }
        if (t == 0) { s1[0] = a; s2[0] = b; }
    }
    __syncthreads();
    float mu   = s1[0] * (1.0f / HDIM);
    float var  = s2[0] * (1.0f / HDIM) - mu * mu;
    float rstd = rsqrtf(var + 1e-6f);
    size_t o = (size_t)row * HDIM;
    float vv[3] = {v0, v1, v2};
    #pragma unroll
    for (int j = 0; j < 3; j++) {
        int idx = t + j * 256;
        float y = (vv[j] - mu) * rstd * gamma[idx] + beta[idx];
        O[o + idx] = __float2half(y);
    }
}

// ---------------------------------------------------------------------------
// Criss-cross attention core (half2-vectorized)
// ---------------------------------------------------------------------------
__global__ void attn_kernel(const __half* __restrict__ qkv,
                            __half* __restrict__ C)
{
    long i = (long)blockIdx.x * blockDim.x + threadIdx.x;
    int  kfp   = (int)(i & 127);
    long token = i >> 7;
    const __half* base = qkv + token * (NCH * 3 * KFAC) + 2 * kfp;
    float2 q[3], k[3], v[3];
    #pragma unroll
    for (int c = 0; c < 3; c++) {
        q[c] = __half22float2(*(const __half2*)(base + c * 768));
        k[c] = __half22float2(*(const __half2*)(base + c * 768 + 256));
        v[c] = __half22float2(*(const __half2*)(base + c * 768 + 512));
    }
    const float sc = 0.0625f;
    float ox[3] = {0.f, 0.f, 0.f}, oy[3] = {0.f, 0.f, 0.f};
    #pragma unroll
    for (int c = 0; c < 3; c++) {
        {
            float s0 = q[c].x * k[0].x * sc, s1 = q[c].x * k[1].x * sc, s2 = q[c].x * k[2].x * sc;
            float m  = fmaxf(s0, fmaxf(s1, s2));
            float e0 = expf(s0 - m), e1 = expf(s1 - m), e2 = expf(s2 - m);
            float w  = v[c].x / (e0 + e1 + e2);
            ox[0] = fmaf(e0, w, ox[0]); ox[1] = fmaf(e1, w, ox[1]); ox[2] = fmaf(e2, w, ox[2]);
        }
        {
            float s0 = q[c].y * k[0].y * sc, s1 = q[c].y * k[1].y * sc, s2 = q[c].y * k[2].y * sc;
            float m  = fmaxf(s0, fmaxf(s1, s2));
            float e0 = expf(s0 - m), e1 = expf(s1 - m), e2 = expf(s2 - m);
            float w  = v[c].y / (e0 + e1 + e2);
            oy[0] = fmaf(e0, w, oy[0]); oy[1] = fmaf(e1, w, oy[1]); oy[2] = fmaf(e2, w, oy[2]);
        }
    }
    __half* cb = C + token * (NCH * KFAC) + 2 * kfp;
    #pragma unroll
    for (int d = 0; d < 3; d++)
        *(__half2*)(cb + d * 256) = __floats2half2_rn(ox[d], oy[d]);
}

// ---------------------------------------------------------------------------
// Weight transpose:  W [K, N] fp32  ->  T [N, K] fp16  (pitch = K)
// ---------------------------------------------------------------------------
__global__ void wprep_kernel(const float* __restrict__ W, long sW, int K, int N,
                             __half* __restrict__ Th, long sT)
{
    __shared__ float tile[32][33];
    const float* Wb = W + (long)blockIdx.z * sW;
    int k0 = blockIdx.x * 32, n0 = blockIdx.y * 32;
    int tx = threadIdx.x, ty = threadIdx.y;
    #pragma unroll
    for (int i = 0; i < 32; i += 8)
        tile[ty + i][tx] = Wb[(size_t)(k0 + ty + i) * N + n0 + tx];
    __syncthreads();
    #pragma unroll
    for (int i = 0; i < 32; i += 8) {
        float v = tile[tx][ty + i];
        size_t o = (size_t)blockIdx.z * sT + (size_t)(n0 + ty + i) * K + (k0 + tx);
        Th[o] = __float2half(v);
    }
}

// ---------------------------------------------------------------------------
// SLIM GEMM: CTA tile 128x64, 8 warps (2x4 of 64x16), 256 threads, 4-stage
// rotated pipeline, ~80 regs -> 3 CTAs/SM = 24 warps/SM. B-frag loaded first.
// EPI: 0 = +bias -> fp16 ; 1 = +bias+residual -> fp32 ; 2 = +bias+GELU -> fp16
// ---------------------------------------------------------------------------
#define ROWB   80
#define T_A    0
#define T_B    10240
#define STAGE  15360
#define GEMM_SMEM (4 * STAGE)

__device__ __forceinline__ void load_stage(
    const __half* __restrict__ A, long lda,
    const __half* __restrict__ B, long ldb,
    long kc, uint32_t sbase, int t)
{
    #pragma unroll
    for (int i = 0; i < 3; i++) {
        int o    = t + (i << 8);
        int row  = o >> 2;
        int part = o & 3;
        const __half* src; uint32_t dst;
        if (row < 128) { src = A + (long)row * lda + kc + part * 8;
                         dst = sbase + T_A + (uint32_t)row * ROWB + part * 16; }
        else           { src = B + (long)(row - 128) * ldb + kc + part * 8;
                         dst = sbase + T_B + (uint32_t)(row - 128) * ROWB + part * 16; }
        CP_ASYNC16(dst, src);
    }
}

template<int EPI>
__global__ void __launch_bounds__(256, 3) gemm_slim(
    const __half* __restrict__ A, int lda, long strideA,
    const __half* __restrict__ B, int ldb, long strideB,
    float* __restrict__ Cf, __half* __restrict__ Ch,
    int ldc, long strideC,
    const float* __restrict__ bias, long strideBias,
    const float* __restrict__ R,
    int K)
{
    extern __shared__ __align__(128) char smem[];
    uint32_t sb = smem_u32(smem);
    int t = threadIdx.x, lane = t & 31, wid = t >> 5;
    int warp_m = wid >> 2, warp_n = wid & 3;
    long m0 = (long)blockIdx.y * 128;
    int  n0 = blockIdx.x * 64;
    long z  = blockIdx.z;

    const __half* Ap = A + z * strideA + m0 * lda;
    const __half* Bp = B + z * strideB + (long)n0 * ldb;

    float acc[4][2][4];
    #pragma unroll
    for (int i = 0; i < 4; i++)
        #pragma unroll
        for (int j = 0; j < 2; j++)
            #pragma unroll
            for (int k = 0; k < 4; k++) acc[i][j][k] = 0.f;

    const int KT = K >> 5;

    load_stage(Ap, lda, Bp, ldb, 0,  sb,             t);
    CP_COMMIT();
    load_stage(Ap, lda, Bp, ldb, 32, sb + STAGE,     t);
    CP_COMMIT();
    load_stage(Ap, lda, Bp, ldb, 64, sb + 2 * STAGE, t);
    CP_COMMIT();
    CP_WAIT2();
    __syncthreads();

    uint32_t lm   = (uint32_t)(lane & 15) * ROWB + (lane >> 4) * 16;
    uint32_t aoff = (uint32_t)(warp_m * 64) * ROWB + lm;
    uint32_t boff = (uint32_t)T_B + (uint32_t)(warp_n * 16) * ROWB + lm;

    #pragma unroll 2
    for (int kt = 0; kt < KT; kt++) {
        uint32_t stg = sb + (uint32_t)(kt & 3) * STAGE;
        uint32_t ka = stg + aoff;
        uint32_t kb = stg + boff;

        uint32_t ah[4][4], bh[4];
        // kh = 0 : B first (feeds all MMAs), then A
        LDSM4(bh[0], bh[1], bh[2], bh[3], kb);
        #pragma unroll
        for (int tm = 0; tm < 4; tm++)
            LDSM4(ah[tm][0], ah[tm][1], ah[tm][2], ah[tm][3], ka + tm * (16 * ROWB));
        #pragma unroll
        for (int tm = 0; tm < 4; tm++)
            #pragma unroll
            for (int tn = 0; tn < 2; tn++)
                MMA_F16(acc[tm][tn], ah[tm], bh[tn], bh[tn + 2]);

        // prefetch kt+3 in MMA shadow
        if (kt + 3 < KT)
            load_stage(Ap, lda, Bp, ldb, (long)(kt + 3) << 5,
                       sb + (uint32_t)((kt + 3) & 3) * STAGE, t);
        CP_COMMIT();

        // kh = 1
        LDSM4(bh[0], bh[1], bh[2], bh[3], kb + 32);
        #pragma unroll
        for (int tm = 0; tm < 4; tm++)
            LDSM4(ah[tm][0], ah[tm][1], ah[tm][2], ah[tm][3], ka + 32 + tm * (16 * ROWB));
        #pragma unroll
        for (int tm = 0; tm < 4; tm++)
            #pragma unroll
            for (int tn = 0; tn < 2; tn++)
                MMA_F16(acc[tm][tn], ah[tm], bh[tn], bh[tn + 2]);

        CP_WAIT2();
        __syncthreads();
    }

    const float* biasb = bias + z * strideBias;
    #pragma unroll
    for (int tm = 0; tm < 4; tm++) {
        #pragma unroll
        for (int tn = 0; tn < 2; tn++) {
            long r = m0 + warp_m * 64 + tm * 16 + (lane >> 2);
            int  c = n0 + warp_n * 16 + tn * 8 + (lane & 3) * 2;
            float b0 = biasb[c], b1 = biasb[c + 1];
            float v0 = acc[tm][tn][0] + b0, v1 = acc[tm][tn][1] + b1;
            float v2 = acc[tm][tn][2] + b0, v3 = acc[tm][tn][3] + b1;
            if (EPI == 1) {
                float* p0 = Cf + z * strideC + r * ldc + c;
                float* p1 = Cf + z * strideC + (r + 8) * ldc + c;
                float2 r0 = *(const float2*)(R + r * ldc + c);
                float2 r1 = *(const float2*)(R + (r + 8) * ldc + c);
                v0 += r0.x; v1 += r0.y; v2 += r1.x; v3 += r1.y;
                *(float2*)p0 = make_float2(v0, v1);
                *(float2*)p1 = make_float2(v2, v3);
            } else {
                if (EPI == 2) {
                    v0 = 0.5f * v0 * (1.0f + erff(v0 * 0.70710678118654752f));
                    v1 = 0.5f * v1 * (1.0f + erff(v1 * 0.70710678118654752f));
                    v2 = 0.5f * v2 * (1.0f + erff(v2 * 0.70710678118654752f));
                    v3 = 0.5f * v3 * (1.0f + erff(v3 * 0.70710678118654752f));
                }
                __half* q0 = Ch + z * strideC + r * ldc + c;
                __half* q1 = Ch + z * strideC + (r + 8) * ldc + c;
                *(__half2*)q0 = __half2{__float2half(v0), __float2half(v1)};
                *(__half2*)q1 = __half2{__float2half(v2), __float2half(v3)};
            }
        }
    }
}

// ---------------------------------------------------------------------------
// Launch — QKV GEMM is launch #4 (the one ncu captures)
// ---------------------------------------------------------------------------
extern "C" void kernel_launch(void* const* d_in, const int* in_sizes, int n_in,
                              void* d_out, int out_size)
{
    const float* x      = (const float*)d_in[0];
    const float* W_qkv  = (const float*)d_in[1];
    const float* b_qkv  = (const float*)d_in[2];
    const float* W_out  = (const float*)d_in[3];
    const float* b_out  = (const float*)d_in[4];
    const float* ln1_g  = (const float*)d_in[5];
    const float* ln1_b  = (const float*)d_in[6];
    const float* ln2_g  = (const float*)d_in[7];
    const float* ln2_b  = (const float*)d_in[8];
    const float* W1     = (const float*)d_in[9];
    const float* b1     = (const float*)d_in[10];
    const float* W2     = (const float*)d_in[11];
    const float* b2     = (const float*)d_in[12];
    float* out = (float*)d_out;

    __half* hb = nullptr; float* xr = nullptr;
    cudaGetSymbolAddress((void**)&hb, g_half);
    cudaGetSymbolAddress((void**)&xr, g_f32);

    cudaFuncSetAttribute(gemm_slim<0>, cudaFuncAttributeMaxDynamicSharedMemorySize, GEMM_SMEM);
    cudaFuncSetAttribute(gemm_slim<1>, cudaFuncAttributeMaxDynamicSharedMemorySize, GEMM_SMEM);
    cudaFuncSetAttribute(gemm_slim<2>, cudaFuncAttributeMaxDynamicSharedMemorySize, GEMM_SMEM);

    dim3 tb(32, 8);
    // 1: LN1
    ln_kernel<<<NL, 256>>>(x, ln1_g, ln1_b, hb + B_H);
    // 2-3: QKV / out-proj weight prep
    wprep_kernel<<<dim3(KFAC / 32, HDIM / 32, NCH), tb>>>(W_qkv, (long)KFAC * HDIM, KFAC, HDIM,
                                                          hb + B_WQT, (long)HDIM * KFAC);
    wprep_kernel<<<dim3(KFAC / 32, KFAC / 32, 1), tb>>>(W_out, 0, KFAC, KFAC, hb + B_WOT, 0);

    // 4: QKV GEMM (PROFILED): per channel [32768 x 768], K=256 (WQT pitch = KFAC)
    gemm_slim<0><<<dim3(HDIM / 64, NL / 128, NCH), 256, GEMM_SMEM>>>(
        hb + B_H, HDIM, (long)KFAC,
        hb + B_WQT, KFAC, (long)HDIM * KFAC,
        nullptr, hb + B_QKV, NCH * HDIM, (long)HDIM,
        b_qkv, (long)HDIM, nullptr, KFAC);

    // 5: attention core (half2)
    attn_kernel<<<(NL * KFAC / 2) / 256, 256>>>(hb + B_QKV, hb + B_CTX);

    // 6: out-proj + bias + residual x -> xr (fp32)  (WOT pitch = KFAC)
    gemm_slim<1><<<dim3(KFAC / 64, (NL * NCH) / 128, 1), 256, GEMM_SMEM>>>(
        hb + B_CTX, KFAC, 0L,
        hb + B_WOT, KFAC, 0L,
        xr, nullptr, KFAC, 0L,
        b_out, 0L, x, KFAC);

    // 7: LN2
    ln_kernel<<<NL, 256>>>(xr, ln2_g, ln2_b, hb + B_Y);

    // 8-9: MLP weight prep
    wprep_kernel<<<dim3(HDIM / 32, MDIM / 32, 1), tb>>>(W1, 0, HDIM, MDIM, hb + B_W1T, 0);
    wprep_kernel<<<dim3(MDIM / 32, HDIM / 32, 1), tb>>>(W2, 0, MDIM, HDIM, hb + B_W2T, 0);

    // 10: MLP up + GELU -> hid fp16 (W1T pitch = HDIM = K)
    gemm_slim<2><<<dim3(MDIM / 64, NL / 128, 1), 256, GEMM_SMEM>>>(
        hb + B_Y, HDIM, 0L,
        hb + B_W1T, HDIM, 0L,
        nullptr, hb + B_HID, MDIM, 0L,
        b1, 0L, nullptr, HDIM);

    // 11: MLP down + bias + residual xr -> out (W2T pitch = MDIM = K)
    gemm_slim<1><<<dim3(HDIM / 64, NL / 128, 1), 256, GEMM_SMEM>>>(
        hb + B_HID, MDIM, 0L,
        hb + B_W2T, MDIM, 0L,
        out, nullptr, HDIM, 0L,
        b2, 0L, xr, MDIM);
}

// round 17
// speedup vs baseline: 1.0313x; 1.0313x over previous
#include <cuda_runtime.h>
#include <cuda_fp16.h>
#include <math.h>
#include <stdint.h>

#define NL   32768
#define HDIM 768
#define KFAC 256
#define NCH  3
#define MDIM 3072

// ---------------------------------------------------------------------------
// Scratch
// ---------------------------------------------------------------------------
static const long S_H    = (long)NL * HDIM;
static const long S_QKV  = (long)NL * 3 * HDIM;
static const long S_HID  = (long)NL * MDIM;
static const long W1T_SZ = (long)HDIM * MDIM;
static const long WQT_SZ = (long)NCH * HDIM * KFAC;

__device__ __half g_half[260046848];
__device__ float  g_f32[25165824];

#define B_H    0L
#define B_CTX  (S_H)
#define B_Y    (2*S_H)
#define B_QKV  (3*S_H)
#define B_HID  (3*S_H + S_QKV)
#define B_W1T  (B_HID + S_HID)
#define B_W2T  (B_W1T + W1T_SZ)
#define B_WQT  (B_W2T + W1T_SZ)
#define B_WOT  (B_WQT + WQT_SZ)

// ---------------------------------------------------------------------------
// PTX helpers
// ---------------------------------------------------------------------------
__device__ __forceinline__ uint32_t smem_u32(const void* p) {
    uint32_t a;
    asm("{ .reg .u64 t; cvta.to.shared.u64 t, %1; cvt.u32.u64 %0, t; }" : "=r"(a) : "l"(p));
    return a;
}
#define CP_ASYNC16(dst, src) \
    asm volatile("cp.async.cg.shared.global [%0], [%1], 16;" :: "r"(dst), "l"(src))
#define CP_COMMIT() asm volatile("cp.async.commit_group;" ::: "memory")
#define CP_WAIT2()  asm volatile("cp.async.wait_group 2;" ::: "memory")

#define LDSM4(r0, r1, r2, r3, a) \
    asm volatile("ldmatrix.sync.aligned.m8n8.x4.shared.b16 {%0,%1,%2,%3}, [%4];" \
        : "=r"(r0), "=r"(r1), "=r"(r2), "=r"(r3) : "r"(a))

#define MMA_F16(c, a, b0, b1) \
    asm volatile("mma.sync.aligned.m16n8k16.row.col.f32.f16.f16.f32 " \
        "{%0,%1,%2,%3}, {%4,%5,%6,%7}, {%8,%9}, {%0,%1,%2,%3};" \
        : "+f"((c)[0]), "+f"((c)[1]), "+f"((c)[2]), "+f"((c)[3]) \
        : "r"((a)[0]), "r"((a)[1]), "r"((a)[2]), "r"((a)[3]), "r"(b0), "r"(b1))

// ---------------------------------------------------------------------------
// LayerNorm -> fp16
// ---------------------------------------------------------------------------
__global__ void ln_kernel(const float* __restrict__ X,
                          const float* __restrict__ gamma,
                          const float* __restrict__ beta,
                          __half* __restrict__ O)
{
    __shared__ float s1[8], s2[8];
    int row = blockIdx.x, t = threadIdx.x;
    const float* xr = X + (size_t)row * HDIM;
    float v0 = xr[t], v1 = xr[t + 256], v2 = xr[t + 512];
    float s  = v0 + v1 + v2;
    float ss = v0 * v0 + v1 * v1 + v2 * v2;
    #pragma unroll
    for (int o = 16; o > 0; o >>= 1) {
        s  += __shfl_down_sync(0xffffffffu, s, o);
        ss += __shfl_down_sync(0xffffffffu, ss, o);
    }
    if ((t & 31) == 0) { s1[t >> 5] = s; s2[t >> 5] = ss; }
    __syncthreads();
    if (t < 32) {
        float a = (t < 8) ? s1[t] : 0.f;
        float b = (t < 8) ? s2[t] : 0.f;
        #pragma unroll
        for (int o = 4; o > 0; o >>= 1) {
            a += __shfl_down_sync(0xffffffffu, a, o);
            b += __shfl_down_sync(0xffffffffu, b, o);
        }
        if (t == 0) { s1[0] = a; s2[0] = b; }
    }
    __syncthreads();
    float mu   = s1[0] * (1.0f / HDIM);
    float var  = s2[0] * (1.0f / HDIM) - mu * mu;
    float rstd = rsqrtf(var + 1e-6f);
    size_t o = (size_t)row * HDIM;
    float vv[3] = {v0, v1, v2};
    #pragma unroll
    for (int j = 0; j < 3; j++) {
        int idx = t + j * 256;
        float y = (vv[j] - mu) * rstd * gamma[idx] + beta[idx];
        O[o + idx] = __float2half(y);
    }
}

// ---------------------------------------------------------------------------
// Criss-cross attention core (half2-vectorized)
// ---------------------------------------------------------------------------
__global__ void attn_kernel(const __half* __restrict__ qkv,
                            __half* __restrict__ C)
{
    long i = (long)blockIdx.x * blockDim.x + threadIdx.x;
    int  kfp   = (int)(i & 127);
    long token = i >> 7;
    const __half* base = qkv + token * (NCH * 3 * KFAC) + 2 * kfp;
    float2 q[3], k[3], v[3];
    #pragma unroll
    for (int c = 0; c < 3; c++) {
        q[c] = __half22float2(*(const __half2*)(base + c * 768));
        k[c] = __half22float2(*(const __half2*)(base + c * 768 + 256));
        v[c] = __half22float2(*(const __half2*)(base + c * 768 + 512));
    }
    const float sc = 0.0625f;
    float ox[3] = {0.f, 0.f, 0.f}, oy[3] = {0.f, 0.f, 0.f};
    #pragma unroll
    for (int c = 0; c < 3; c++) {
        {
            float s0 = q[c].x * k[0].x * sc, s1 = q[c].x * k[1].x * sc, s2 = q[c].x * k[2].x * sc;
            float m  = fmaxf(s0, fmaxf(s1, s2));
            float e0 = expf(s0 - m), e1 = expf(s1 - m), e2 = expf(s2 - m);
            float w  = v[c].x / (e0 + e1 + e2);
            ox[0] = fmaf(e0, w, ox[0]); ox[1] = fmaf(e1, w, ox[1]); ox[2] = fmaf(e2, w, ox[2]);
        }
        {
            float s0 = q[c].y * k[0].y * sc, s1 = q[c].y * k[1].y * sc, s2 = q[c].y * k[2].y * sc;
            float m  = fmaxf(s0, fmaxf(s1, s2));
            float e0 = expf(s0 - m), e1 = expf(s1 - m), e2 = expf(s2 - m);
            float w  = v[c].y / (e0 + e1 + e2);
            oy[0] = fmaf(e0, w, oy[0]); oy[1] = fmaf(e1, w, oy[1]); oy[2] = fmaf(e2, w, oy[2]);
        }
    }
    __half* cb = C + token * (NCH * KFAC) + 2 * kfp;
    #pragma unroll
    for (int d = 0; d < 3; d++)
        *(__half2*)(cb + d * 256) = __floats2half2_rn(ox[d], oy[d]);
}

// ---------------------------------------------------------------------------
// Weight transpose:  W [K, N] fp32  ->  T [N, K] fp16  (pitch = K)
// ---------------------------------------------------------------------------
__global__ void wprep_kernel(const float* __restrict__ W, long sW, int K, int N,
                             __half* __restrict__ Th, long sT)
{
    __shared__ float tile[32][33];
    const float* Wb = W + (long)blockIdx.z * sW;
    int k0 = blockIdx.x * 32, n0 = blockIdx.y * 32;
    int tx = threadIdx.x, ty = threadIdx.y;
    #pragma unroll
    for (int i = 0; i < 32; i += 8)
        tile[ty + i][tx] = Wb[(size_t)(k0 + ty + i) * N + n0 + tx];
    __syncthreads();
    #pragma unroll
    for (int i = 0; i < 32; i += 8) {
        float v = tile[tx][ty + i];
        size_t o = (size_t)blockIdx.z * sT + (size_t)(n0 + ty + i) * K + (k0 + tx);
        Th[o] = __float2half(v);
    }
}

// ---------------------------------------------------------------------------
// SLIM GEMM: CTA tile 128x64, 8 warps (2x4 of 64x16), 256 threads, 4-stage
// rotated pipeline. ~80 regs -> 3 CTAs/SM = 24 warps/SM.
// EPI: 0 = +bias -> fp16 ; 1 = +bias+residual -> fp32 ; 2 = +bias+GELU -> fp16
// ---------------------------------------------------------------------------
#define ROWB   80
#define T_A    0
#define T_B    10240
#define STAGE  15360
#define GEMM_SMEM (4 * STAGE)

__device__ __forceinline__ void load_stage(
    const __half* __restrict__ A, long lda,
    const __half* __restrict__ B, long ldb,
    long kc, uint32_t sbase, int t)
{
    #pragma unroll
    for (int i = 0; i < 3; i++) {
        int o    = t + (i << 8);
        int row  = o >> 2;
        int part = o & 3;
        const __half* src; uint32_t dst;
        if (row < 128) { src = A + (long)row * lda + kc + part * 8;
                         dst = sbase + T_A + (uint32_t)row * ROWB + part * 16; }
        else           { src = B + (long)(row - 128) * ldb + kc + part * 8;
                         dst = sbase + T_B + (uint32_t)(row - 128) * ROWB + part * 16; }
        CP_ASYNC16(dst, src);
    }
}

template<int EPI>
__global__ void __launch_bounds__(256, 3) gemm_slim(
    const __half* __restrict__ A, int lda, long strideA,
    const __half* __restrict__ B, int ldb, long strideB,
    float* __restrict__ Cf, __half* __restrict__ Ch,
    int ldc, long strideC,
    const float* __restrict__ bias, long strideBias,
    const float* __restrict__ R,
    int K)
{
    extern __shared__ __align__(128) char smem[];
    uint32_t sb = smem_u32(smem);
    int t = threadIdx.x, lane = t & 31, wid = t >> 5;
    int warp_m = wid >> 2, warp_n = wid & 3;
    long m0 = (long)blockIdx.y * 128;
    int  n0 = blockIdx.x * 64;
    long z  = blockIdx.z;

    const __half* Ap = A + z * strideA + m0 * lda;
    const __half* Bp = B + z * strideB + (long)n0 * ldb;

    float acc[4][2][4];
    #pragma unroll
    for (int i = 0; i < 4; i++)
        #pragma unroll
        for (int j = 0; j < 2; j++)
            #pragma unroll
            for (int k = 0; k < 4; k++) acc[i][j][k] = 0.f;

    const int KT = K >> 5;

    load_stage(Ap, lda, Bp, ldb, 0,  sb,             t);
    CP_COMMIT();
    load_stage(Ap, lda, Bp, ldb, 32, sb + STAGE,     t);
    CP_COMMIT();
    load_stage(Ap, lda, Bp, ldb, 64, sb + 2 * STAGE, t);
    CP_COMMIT();
    CP_WAIT2();
    __syncthreads();

    uint32_t lm   = (uint32_t)(lane & 15) * ROWB + (lane >> 4) * 16;
    uint32_t aoff = (uint32_t)(warp_m * 64) * ROWB + lm;
    uint32_t boff = (uint32_t)T_B + (uint32_t)(warp_n * 16) * ROWB + lm;

    for (int kt = 0; kt < KT; kt++) {
        uint32_t stg = sb + (uint32_t)(kt & 3) * STAGE;
        uint32_t ka = stg + aoff;
        uint32_t kb = stg + boff;

        uint32_t ah[4][4], bh[4];
        #pragma unroll
        for (int tm = 0; tm < 4; tm++)
            LDSM4(ah[tm][0], ah[tm][1], ah[tm][2], ah[tm][3], ka + tm * (16 * ROWB));
        LDSM4(bh[0], bh[1], bh[2], bh[3], kb);
        #pragma unroll
        for (int tm = 0; tm < 4; tm++)
            #pragma unroll
            for (int tn = 0; tn < 2; tn++)
                MMA_F16(acc[tm][tn], ah[tm], bh[tn], bh[tn + 2]);

        if (kt + 3 < KT)
            load_stage(Ap, lda, Bp, ldb, (long)(kt + 3) << 5,
                       sb + (uint32_t)((kt + 3) & 3) * STAGE, t);
        CP_COMMIT();

        #pragma unroll
        for (int tm = 0; tm < 4; tm++)
            LDSM4(ah[tm][0], ah[tm][1], ah[tm][2], ah[tm][3], ka + 32 + tm * (16 * ROWB));
        LDSM4(bh[0], bh[1], bh[2], bh[3], kb + 32);
        #pragma unroll
        for (int tm = 0; tm < 4; tm++)
            #pragma unroll
            for (int tn = 0; tn < 2; tn++)
                MMA_F16(acc[tm][tn], ah[tm], bh[tn], bh[tn + 2]);

        CP_WAIT2();
        __syncthreads();
    }

    const float* biasb = bias + z * strideBias;
    #pragma unroll
    for (int tm = 0; tm < 4; tm++) {
        #pragma unroll
        for (int tn = 0; tn < 2; tn++) {
            long r = m0 + warp_m * 64 + tm * 16 + (lane >> 2);
            int  c = n0 + warp_n * 16 + tn * 8 + (lane & 3) * 2;
            float b0 = biasb[c], b1 = biasb[c + 1];
            float v0 = acc[tm][tn][0] + b0, v1 = acc[tm][tn][1] + b1;
            float v2 = acc[tm][tn][2] + b0, v3 = acc[tm][tn][3] + b1;
            if (EPI == 1) {
                float* p0 = Cf + z * strideC + r * ldc + c;
                float* p1 = Cf + z * strideC + (r + 8) * ldc + c;
                float2 r0 = *(const float2*)(R + r * ldc + c);
                float2 r1 = *(const float2*)(R + (r + 8) * ldc + c);
                v0 += r0.x; v1 += r0.y; v2 += r1.x; v3 += r1.y;
                *(float2*)p0 = make_float2(v0, v1);
                *(float2*)p1 = make_float2(v2, v3);
            } else {
                if (EPI == 2) {
                    v0 = 0.5f * v0 * (1.0f + erff(v0 * 0.70710678118654752f));
                    v1 = 0.5f * v1 * (1.0f + erff(v1 * 0.70710678118654752f));
                    v2 = 0.5f * v2 * (1.0f + erff(v2 * 0.70710678118654752f));
                    v3 = 0.5f * v3 * (1.0f + erff(v3 * 0.70710678118654752f));
                }
                __half* q0 = Ch + z * strideC + r * ldc + c;
                __half* q1 = Ch + z * strideC + (r + 8) * ldc + c;
                *(__half2*)q0 = __half2{__float2half(v0), __float2half(v1)};
                *(__half2*)q1 = __half2{__float2half(v2), __float2half(v3)};
            }
        }
    }
}

// ---------------------------------------------------------------------------
// Launch — QKV GEMM is launch #4 (the one ncu captures)
// ---------------------------------------------------------------------------
extern "C" void kernel_launch(void* const* d_in, const int* in_sizes, int n_in,
                              void* d_out, int out_size)
{
    const float* x      = (const float*)d_in[0];
    const float* W_qkv  = (const float*)d_in[1];
    const float* b_qkv  = (const float*)d_in[2];
    const float* W_out  = (const float*)d_in[3];
    const float* b_out  = (const float*)d_in[4];
    const float* ln1_g  = (const float*)d_in[5];
    const float* ln1_b  = (const float*)d_in[6];
    const float* ln2_g  = (const float*)d_in[7];
    const float* ln2_b  = (const float*)d_in[8];
    const float* W1     = (const float*)d_in[9];
    const float* b1     = (const float*)d_in[10];
    const float* W2     = (const float*)d_in[11];
    const float* b2     = (const float*)d_in[12];
    float* out = (float*)d_out;

    __half* hb = nullptr; float* xr = nullptr;
    cudaGetSymbolAddress((void**)&hb, g_half);
    cudaGetSymbolAddress((void**)&xr, g_f32);

    cudaFuncSetAttribute(gemm_slim<0>, cudaFuncAttributeMaxDynamicSharedMemorySize, GEMM_SMEM);
    cudaFuncSetAttribute(gemm_slim<1>, cudaFuncAttributeMaxDynamicSharedMemorySize, GEMM_SMEM);
    cudaFuncSetAttribute(gemm_slim<2>, cudaFuncAttributeMaxDynamicSharedMemorySize, GEMM_SMEM);

    dim3 tb(32, 8);
    // 1: LN1
    ln_kernel<<<NL, 256>>>(x, ln1_g, ln1_b, hb + B_H);
    // 2-3: QKV / out-proj weight prep
    wprep_kernel<<<dim3(KFAC / 32, HDIM / 32, NCH), tb>>>(W_qkv, (long)KFAC * HDIM, KFAC, HDIM,
                                                          hb + B_WQT, (long)HDIM * KFAC);
    wprep_kernel<<<dim3(KFAC / 32, KFAC / 32, 1), tb>>>(W_out, 0, KFAC, KFAC, hb + B_WOT, 0);

    // 4: QKV GEMM (PROFILED): per channel [32768 x 768], K=256 (WQT pitch = KFAC)
    gemm_slim<0><<<dim3(HDIM / 64, NL / 128, NCH), 256, GEMM_SMEM>>>(
        hb + B_H, HDIM, (long)KFAC,
        hb + B_WQT, KFAC, (long)HDIM * KFAC,
        nullptr, hb + B_QKV, NCH * HDIM, (long)HDIM,
        b_qkv, (long)HDIM, nullptr, KFAC);

    // 5: attention core (half2)
    attn_kernel<<<(NL * KFAC / 2) / 256, 256>>>(hb + B_QKV, hb + B_CTX);

    // 6: out-proj + bias + residual x -> xr (fp32)  (WOT pitch = KFAC)
    gemm_slim<1><<<dim3(KFAC / 64, (NL * NCH) / 128, 1), 256, GEMM_SMEM>>>(
        hb + B_CTX, KFAC, 0L,
        hb + B_WOT, KFAC, 0L,
        xr, nullptr, KFAC, 0L,
        b_out, 0L, x, KFAC);

    // 7: LN2
    ln_kernel<<<NL, 256>>>(xr, ln2_g, ln2_b, hb + B_Y);

    // 8-9: MLP weight prep
    wprep_kernel<<<dim3(HDIM / 32, MDIM / 32, 1), tb>>>(W1, 0, HDIM, MDIM, hb + B_W1T, 0);
    wprep_kernel<<<dim3(MDIM / 32, HDIM / 32, 1), tb>>>(W2, 0, MDIM, HDIM, hb + B_W2T, 0);

    // 10: MLP up + GELU -> hid fp16 (W1T pitch = HDIM = K)
    gemm_slim<2><<<dim3(MDIM / 64, NL / 128, 1), 256, GEMM_SMEM>>>(
        hb + B_Y, HDIM, 0L,
        hb + B_W1T, HDIM, 0L,
        nullptr, hb + B_HID, MDIM, 0L,
        b1, 0L, nullptr, HDIM);

    // 11: MLP down + bias + residual xr -> out (W2T pitch = MDIM = K)
    gemm_slim<1><<<dim3(HDIM / 64, NL / 128, 1), 256, GEMM_SMEM>>>(
        hb + B_HID, MDIM, 0L,
        hb + B_W2T, MDIM, 0L,
        out, nullptr, HDIM, 0L,
        b2, 0L, xr, MDIM);
}